// round 1
// baseline (speedup 1.0000x reference)
#include <cuda_runtime.h>

// Problem constants
#define BATCH 8
#define S 160              // D = H = W = 160
#define PLANE (S * S)      // 25600
#define NPAIR (S - 1)      // 159
#define NACC (BATCH * NPAIR)  // 1272

// Per-(batch, slice-pair) squared-distance accumulators for the 3 axes.
// Device globals (no allocation allowed); zeroed by a kernel each launch.
__device__ float g_sqD[NACC];
__device__ float g_sqH[NACC];
__device__ float g_sqW[NACC];

__global__ void zero_acc_kernel() {
    int i = blockIdx.x * blockDim.x + threadIdx.x;
    if (i < NACC) {
        g_sqD[i] = 0.0f;
        g_sqH[i] = 0.0f;
        g_sqW[i] = 0.0f;
    }
}

// One block per (b, d) plane. 160 threads; thread = column w.
// Loops h: carries previous-row value in a register (H diff),
// gets w+1 neighbor via shfl (+ lane31 patch load, L1 hit),
// reads plane d+1 for the D diff (L2-resident: neighbor block's primary plane).
__global__ void __launch_bounds__(S) main_pass_kernel(const float* __restrict__ x) {
    const int d = blockIdx.x;
    const int b = blockIdx.y;
    const int w = threadIdx.x;          // 0..159
    const int lane = w & 31;
    const int warp = w >> 5;            // 0..4

    const float* base  = x + ((size_t)(b * S + d)) * PLANE;   // plane (b, d)
    const float* basen = base + PLANE;                         // plane (b, d+1)
    const bool hasD = (d < S - 1);

    __shared__ float sH[S];     // per-row H partial sums (index = pair h)
    __shared__ float sD[5];     // per-warp D partials
    sH[w] = 0.0f;
    __syncthreads();

    float accW = 0.0f;          // per-thread: fixed w, summed over h
    float accD = 0.0f;          // summed over h,w (block reduce at end)
    float vprev = 0.0f;

    #pragma unroll 4
    for (int h = 0; h < S; ++h) {
        const float v = base[h * S + w];

        // W diff: neighbor column value
        float vn = __shfl_down_sync(0xffffffffu, v, 1);
        if (lane == 31 && w < S - 1) vn = base[h * S + w + 1];  // cross-warp patch (L1 hit)
        if (w < S - 1) {
            const float dw = vn - v;
            accW += dw * dw;
        }

        // D diff: same position, next plane
        if (hasD) {
            const float vd = basen[h * S + w];
            const float dd = vd - v;
            accD += dd * dd;
        }

        // H diff: previous row (register-carried). All 32 lanes of a warp share h
        // -> full-warp butterfly reduce, leader adds to shared per-row slot.
        if (h > 0) {
            const float dh = v - vprev;
            float hv = dh * dh;
            hv += __shfl_xor_sync(0xffffffffu, hv, 16);
            hv += __shfl_xor_sync(0xffffffffu, hv, 8);
            hv += __shfl_xor_sync(0xffffffffu, hv, 4);
            hv += __shfl_xor_sync(0xffffffffu, hv, 2);
            hv += __shfl_xor_sync(0xffffffffu, hv, 1);
            if (lane == 0) atomicAdd(&sH[h - 1], hv);
        }
        vprev = v;
    }

    // D: block reduce (5 warps)
    if (hasD) {
        float r = accD;
        r += __shfl_xor_sync(0xffffffffu, r, 16);
        r += __shfl_xor_sync(0xffffffffu, r, 8);
        r += __shfl_xor_sync(0xffffffffu, r, 4);
        r += __shfl_xor_sync(0xffffffffu, r, 2);
        r += __shfl_xor_sync(0xffffffffu, r, 1);
        if (lane == 0) sD[warp] = r;
    }
    __syncthreads();

    // W: one atomic per thread (160 d-blocks contend per (b,w) address)
    if (w < S - 1) atomicAdd(&g_sqW[b * NPAIR + w], accW);
    // H: one atomic per pair index
    if (w < S - 1) atomicAdd(&g_sqH[b * NPAIR + w], sH[w]);
    // D: unique writer per (b,d) -> plain store
    if (hasD && w == 0) {
        g_sqD[b * NPAIR + d] = sD[0] + sD[1] + sD[2] + sD[3] + sD[4];
    }
}

// Final reduction: RBF kernel per (b, pair) per axis, mean, negate, /3.
__global__ void finalize_kernel(const float* __restrict__ log_sigma,
                                float* __restrict__ out) {
    __shared__ float red[256];
    const int tid = threadIdx.x;

    // c_i = 1 / (2*sigma_i^2) = 0.5 * exp(-2*log_sigma_i)
    const float c0 = 0.5f * expf(-2.0f * log_sigma[0]);  // axis D
    const float c1 = 0.5f * expf(-2.0f * log_sigma[1]);  // axis H
    const float c2 = 0.5f * expf(-2.0f * log_sigma[2]);  // axis W

    float p = 0.0f;
    for (int i = tid; i < NACC; i += 256) {
        p += expf(-g_sqD[i] * c0);
        p += expf(-g_sqH[i] * c1);
        p += expf(-g_sqW[i] * c2);
    }
    red[tid] = p;
    __syncthreads();
    for (int s = 128; s > 0; s >>= 1) {
        if (tid < s) red[tid] += red[tid + s];
        __syncthreads();
    }
    if (tid == 0) out[0] = -red[0] / (float)(NACC * 3);
}

extern "C" void kernel_launch(void* const* d_in, const int* in_sizes, int n_in,
                              void* d_out, int out_size) {
    const float* x = (const float*)d_in[0];          // [8,1,160,160,160] fp32
    const float* log_sigma = (const float*)d_in[1];  // [3] fp32
    float* out = (float*)d_out;                      // scalar fp32

    zero_acc_kernel<<<(NACC + 255) / 256, 256>>>();
    dim3 grid(S, BATCH);  // (d, b)
    main_pass_kernel<<<grid, S>>>(x);
    finalize_kernel<<<1, 256>>>(log_sigma, out);
}

// round 2
// speedup vs baseline: 1.5430x; 1.5430x over previous
#include <cuda_runtime.h>

// Problem: x[8,1,160,160,160] fp32, log_sigma[3] -> scalar RBF slice-smoothness loss.
#define BATCH 8
#define S 160
#define PLANE (S * S)          // 25600
#define NPAIR (S - 1)          // 159
#define NACC (BATCH * NPAIR)   // 1272
#define NBLOCKS (S * BATCH)    // 1280

// Accumulators (device globals; no allocation allowed).
// g_sqD: plain-stored (unique writer per slot) each launch -> no zeroing needed.
// g_sqH/g_sqW: atomic-accumulated; zero-initialized statically, re-zeroed by the
// last block of each launch so every graph replay starts clean.
__device__ float g_sqD[NACC];
__device__ float g_sqH[NACC];
__device__ float g_sqW[NACC];
__device__ unsigned int g_count;   // completion counter; reset by last block

__device__ __forceinline__ float warp_sum(float v) {
    v += __shfl_xor_sync(0xffffffffu, v, 16);
    v += __shfl_xor_sync(0xffffffffu, v, 8);
    v += __shfl_xor_sync(0xffffffffu, v, 4);
    v += __shfl_xor_sync(0xffffffffu, v, 2);
    v += __shfl_xor_sync(0xffffffffu, v, 1);
    return v;
}

// Grid: (160 d-planes, 8 batches). Block: 256 threads = 8 warps.
// Warp wid owns rows h in [20*wid, 20*wid+20) of plane (b,d):
//   - loads each row as float4 (lanes 0..31 cover cols 0..127; lanes 0..7 also cols 128..159)
//   - W diffs: internal to float4 (free) + boundary scalars (L1 hits)
//   - H diffs: previous row register-carried; one 5-shfl butterfly per row -> unique sH slot
//   - D diffs: same-position load from plane d+1 (L2-resident: it's block d+1's own plane)
__global__ void __launch_bounds__(256) fused_kernel(const float* __restrict__ x,
                                                    const float* __restrict__ log_sigma,
                                                    float* __restrict__ out) {
    const int d    = blockIdx.x;
    const int b    = blockIdx.y;
    const int tid  = threadIdx.x;
    const int wid  = tid >> 5;
    const int lane = tid & 31;
    const bool bl  = (lane < 8);     // lanes that own the second float4 segment

    __shared__ float sH[S];          // per-pair H sums for this plane (slot p written by one warp)
    __shared__ float sWp[8][S];      // per-warp W partials, pair-indexed
    __shared__ float sD[8];
    __shared__ float sRed[256];
    __shared__ unsigned int sLast;

    const float* base  = x + ((size_t)(b * S + d)) * PLANE;
    const float* nbase = base + PLANE;
    const bool hasD = (d < S - 1);

    const int h0 = wid * 20;

    float wA0 = 0.f, wA1 = 0.f, wA2 = 0.f, wA3 = 0.f;   // W pairs 4*lane .. 4*lane+3
    float wB0 = 0.f, wB1 = 0.f, wB2 = 0.f, wB3 = 0.f;   // W pairs 128+4*lane .. +3 (lanes<8)
    float accD = 0.f;
    float4 pa = make_float4(0.f, 0.f, 0.f, 0.f);
    float4 pb = make_float4(0.f, 0.f, 0.f, 0.f);

    #pragma unroll 4
    for (int k = 0; k < 20; ++k) {
        const int h = h0 + k;
        const float*  rowf = base + h * S;
        const float4* row4 = (const float4*)rowf;

        const float4 a  = row4[lane];
        const float4 bb = bl ? row4[32 + lane] : make_float4(0.f, 0.f, 0.f, 0.f);
        const float nxa = rowf[4 * lane + 4];                         // col 4*lane+4 (<=128)
        const float nxb = (lane < 7) ? rowf[128 + 4 * lane + 4] : 0.f;

        float t;
        // W diffs (fixed pair indices -> register accumulators)
        t = a.y - a.x; wA0 += t * t;
        t = a.z - a.y; wA1 += t * t;
        t = a.w - a.z; wA2 += t * t;
        t = nxa - a.w; wA3 += t * t;
        if (bl) {
            t = bb.y - bb.x; wB0 += t * t;
            t = bb.z - bb.y; wB1 += t * t;
            t = bb.w - bb.z; wB2 += t * t;
            if (lane < 7) { t = nxb - bb.w; wB3 += t * t; }
        }

        // D diffs vs plane d+1 (same positions)
        if (hasD) {
            const float4* nrow4 = (const float4*)(nbase + h * S);
            const float4 na = nrow4[lane];
            t = na.x - a.x; accD += t * t;
            t = na.y - a.y; accD += t * t;
            t = na.z - a.z; accD += t * t;
            t = na.w - a.w; accD += t * t;
            if (bl) {
                const float4 nb = nrow4[32 + lane];
                t = nb.x - bb.x; accD += t * t;
                t = nb.y - bb.y; accD += t * t;
                t = nb.z - bb.z; accD += t * t;
                t = nb.w - bb.w; accD += t * t;
            }
        }

        // H diffs vs previous (register-carried) row; pair index h-1 owned by this warp
        if (k > 0) {
            float hs;
            t = a.x - pa.x; hs  = t * t;
            t = a.y - pa.y; hs += t * t;
            t = a.z - pa.z; hs += t * t;
            t = a.w - pa.w; hs += t * t;
            if (bl) {
                t = bb.x - pb.x; hs += t * t;
                t = bb.y - pb.y; hs += t * t;
                t = bb.z - pb.z; hs += t * t;
                t = bb.w - pb.w; hs += t * t;
            }
            hs = warp_sum(hs);
            if (lane == 0) sH[h - 1] = hs;
        }
        pa = a; pb = bb;
    }

    // Last H pair of this warp's range: row h0+20 belongs to the next warp -> reload (L1/L2 hit)
    if (h0 + 20 < S) {
        const float*  rowf = base + (h0 + 20) * S;
        const float4* row4 = (const float4*)rowf;
        const float4 a  = row4[lane];
        const float4 bb = bl ? row4[32 + lane] : make_float4(0.f, 0.f, 0.f, 0.f);
        float t, hs;
        t = a.x - pa.x; hs  = t * t;
        t = a.y - pa.y; hs += t * t;
        t = a.z - pa.z; hs += t * t;
        t = a.w - pa.w; hs += t * t;
        if (bl) {
            t = bb.x - pb.x; hs += t * t;
            t = bb.y - pb.y; hs += t * t;
            t = bb.z - pb.z; hs += t * t;
            t = bb.w - pb.w; hs += t * t;
        }
        hs = warp_sum(hs);
        if (lane == 0) sH[h0 + 19] = hs;
    }

    // D: block reduce (one butterfly per warp)
    if (hasD) {
        const float r = warp_sum(accD);
        if (lane == 0) sD[wid] = r;
    }

    // W: per-warp partials to shared (pair-indexed, conflict-free)
    sWp[wid][4 * lane + 0] = wA0;
    sWp[wid][4 * lane + 1] = wA1;
    sWp[wid][4 * lane + 2] = wA2;
    sWp[wid][4 * lane + 3] = wA3;
    if (bl) {
        sWp[wid][128 + 4 * lane + 0] = wB0;
        sWp[wid][128 + 4 * lane + 1] = wB1;
        sWp[wid][128 + 4 * lane + 2] = wB2;
        sWp[wid][128 + 4 * lane + 3] = wB3;   // slot 159 gets 0 (never read)
    }
    __syncthreads();

    // Cross-warp combine + one global atomic per pair
    if (tid < NPAIR) {
        float s = 0.f;
        #pragma unroll
        for (int w = 0; w < 8; ++w) s += sWp[w][tid];
        atomicAdd(&g_sqW[b * NPAIR + tid], s);
        atomicAdd(&g_sqH[b * NPAIR + tid], sH[tid]);
    }
    if (tid == 0 && hasD) {
        g_sqD[b * NPAIR + d] = sD[0] + sD[1] + sD[2] + sD[3]
                             + sD[4] + sD[5] + sD[6] + sD[7];
    }

    // Completion counter: last block finalizes and re-zeroes state for the next replay.
    __threadfence();
    if (tid == 0) sLast = (atomicAdd(&g_count, 1u) == (unsigned)(NBLOCKS - 1));
    __syncthreads();
    if (sLast) {
        const float c0 = 0.5f * __expf(-2.f * log_sigma[0]);  // axis D
        const float c1 = 0.5f * __expf(-2.f * log_sigma[1]);  // axis H
        const float c2 = 0.5f * __expf(-2.f * log_sigma[2]);  // axis W
        float p = 0.f;
        for (int i = tid; i < NACC; i += 256) {
            p += expf(-g_sqD[i] * c0) + expf(-g_sqH[i] * c1) + expf(-g_sqW[i] * c2);
            g_sqH[i] = 0.f;   // reset for next launch
            g_sqW[i] = 0.f;
        }
        sRed[tid] = p;
        __syncthreads();
        #pragma unroll
        for (int s = 128; s > 0; s >>= 1) {
            if (tid < s) sRed[tid] += sRed[tid + s];
            __syncthreads();
        }
        if (tid == 0) {
            out[0] = -sRed[0] / (float)(NACC * 3);
            g_count = 0u;     // reset counter for next launch
        }
    }
}

extern "C" void kernel_launch(void* const* d_in, const int* in_sizes, int n_in,
                              void* d_out, int out_size) {
    const float* x         = (const float*)d_in[0];   // [8,1,160,160,160] fp32
    const float* log_sigma = (const float*)d_in[1];   // [3] fp32
    float* out             = (float*)d_out;           // scalar fp32

    dim3 grid(S, BATCH);   // (d, b)
    fused_kernel<<<grid, 256>>>(x, log_sigma, out);
}